// round 9
// baseline (speedup 1.0000x reference)
#include <cuda_runtime.h>
#include <cuda_fp16.h>
#include <cstdint>

#define CD 768
#define ND 4096
#define BB 8

using fp16 = __half;

// ---------------------------------------------------------------------------
// Device scratch (module-load allocated; no runtime allocs)
// ---------------------------------------------------------------------------
__device__ fp16 g_x1n_hi[(size_t)BB * ND * CD];  // x1 natural [b][n][c]
__device__ fp16 g_x1n_lo[(size_t)BB * ND * CD];
__device__ fp16 g_x2n_hi[(size_t)BB * ND * CD];  // x2 natural [b][n][c]
__device__ fp16 g_x2n_lo[(size_t)BB * ND * CD];
__device__ float g_attn[(size_t)BB * CD * CD];   // fp32 logits
__device__ fp16 g_at_hi[(size_t)BB * CD * CD];   // softmaxed attn (fp16)

__device__ __constant__ float kScale = 0.10206207261596577f;  // (768/8)^-0.5

// ---------------------------------------------------------------------------
// PTX helpers
// ---------------------------------------------------------------------------
__device__ __forceinline__ uint32_t smem_u32(const void* p) {
    uint32_t a;
    asm("{ .reg .u64 t; cvta.to.shared.u64 t, %1; cvt.u32.u64 %0, t; }" : "=r"(a) : "l"(p));
    return a;
}

__device__ __forceinline__ void cp_async16(uint32_t saddr, const void* gaddr) {
    asm volatile("cp.async.cg.shared.global [%0], [%1], 16;" :: "r"(saddr), "l"(gaddr));
}
#define CP_COMMIT() asm volatile("cp.async.commit_group;" ::: "memory")
#define CP_WAIT(n)  asm volatile("cp.async.wait_group %0;" :: "n"(n) : "memory")

__device__ __forceinline__ void ldsm4(uint32_t& r0, uint32_t& r1, uint32_t& r2,
                                      uint32_t& r3, uint32_t addr) {
    asm volatile("ldmatrix.sync.aligned.m8n8.x4.shared.b16 {%0,%1,%2,%3}, [%4];"
                 : "=r"(r0), "=r"(r1), "=r"(r2), "=r"(r3) : "r"(addr));
}
__device__ __forceinline__ void ldsm4t(uint32_t& r0, uint32_t& r1, uint32_t& r2,
                                       uint32_t& r3, uint32_t addr) {
    asm volatile("ldmatrix.sync.aligned.m8n8.x4.trans.shared.b16 {%0,%1,%2,%3}, [%4];"
                 : "=r"(r0), "=r"(r1), "=r"(r2), "=r"(r3) : "r"(addr));
}

__device__ __forceinline__ void mma_f16(float* c, const uint32_t* a, const uint32_t* b) {
    asm volatile(
        "mma.sync.aligned.m16n8k16.row.col.f32.f16.f16.f32 "
        "{%0,%1,%2,%3}, {%4,%5,%6,%7}, {%8,%9}, {%0,%1,%2,%3};"
        : "+f"(c[0]), "+f"(c[1]), "+f"(c[2]), "+f"(c[3])
        : "r"(a[0]), "r"(a[1]), "r"(a[2]), "r"(a[3]), "r"(b[0]), "r"(b[1]));
}

// ---------------------------------------------------------------------------
// Streaming fp16 split, both tensors in one launch.
// First half of blocks -> x1, second half -> x2.
// ---------------------------------------------------------------------------
__global__ __launch_bounds__(256) void split_kernel(const float* __restrict__ x1,
                                                    const float* __restrict__ x2) {
    const int half = gridDim.x >> 1;
    const float* src;
    fp16 *dh, *dl;
    int blk = blockIdx.x;
    if (blk < half) {
        src = x1; dh = g_x1n_hi; dl = g_x1n_lo;
    } else {
        src = x2; dh = g_x2n_hi; dl = g_x2n_lo;
        blk -= half;
    }
    size_t i = ((size_t)blk * 256 + threadIdx.x) * 8;
    float4 v0 = *(const float4*)(src + i);
    float4 v1 = *(const float4*)(src + i + 4);
    float f[8] = {v0.x, v0.y, v0.z, v0.w, v1.x, v1.y, v1.z, v1.w};
    fp16 h[8], l[8];
#pragma unroll
    for (int j = 0; j < 8; j++) {
        h[j] = __float2half_rn(f[j]);
        l[j] = __float2half_rn(f[j] - __half2float(h[j]));
    }
    *(uint4*)(dh + i) = *(uint4*)h;
    *(uint4*)(dl + i) = *(uint4*)l;
}

// ---------------------------------------------------------------------------
// Softmax over g_attn rows -> fp16 attn
// ---------------------------------------------------------------------------
__global__ __launch_bounds__(256) void softmax_kernel() {
    const size_t ro = (size_t)blockIdx.x * CD;
    float* p = g_attn + ro;
    const int tid = threadIdx.x;

    float v0 = p[tid], v1 = p[tid + 256], v2 = p[tid + 512];

    float m = fmaxf(fmaxf(v0, v1), v2);
#pragma unroll
    for (int o = 16; o > 0; o >>= 1) m = fmaxf(m, __shfl_xor_sync(0xffffffffu, m, o));

    __shared__ float sm[8], ss[8];
    if ((tid & 31) == 0) sm[tid >> 5] = m;
    __syncthreads();
    float bm = sm[0];
#pragma unroll
    for (int i = 1; i < 8; i++) bm = fmaxf(bm, sm[i]);

    float e0 = __expf(v0 - bm), e1 = __expf(v1 - bm), e2 = __expf(v2 - bm);
    float s = e0 + e1 + e2;
#pragma unroll
    for (int o = 16; o > 0; o >>= 1) s += __shfl_xor_sync(0xffffffffu, s, o);
    if ((tid & 31) == 0) ss[tid >> 5] = s;
    __syncthreads();
    float bs = 0.f;
#pragma unroll
    for (int i = 0; i < 8; i++) bs += ss[i];

    float inv = 1.0f / bs;
    g_at_hi[ro + tid]       = __float2half_rn(e0 * inv);
    g_at_hi[ro + tid + 256] = __float2half_rn(e1 * inv);
    g_at_hi[ro + tid + 512] = __float2half_rn(e2 * inv);
}

// ---------------------------------------------------------------------------
// GEMM1 (logits): attn[m][n] = scale * sum_k x1[k][m]*x2[k][n], k = seq dim.
// Natural [n][c] operands, ldmatrix.trans fragments.
// CTA 128x128, 256 threads, BK=32, 3-stage, one barrier per chunk;
// cp.async for chunk c+2 issued between ks0 LDSM and ks0 MMA.
// ---------------------------------------------------------------------------
static constexpr int ROW2 = 272;
static constexpr int TEN2 = 32 * ROW2;      // 8704
static constexpr int STG2 = 4 * TEN2;       // 34816
static constexpr int SM1 = 3 * STG2;        // 104448

__global__ __launch_bounds__(256) void gemm1_kernel() {
    extern __shared__ char smc[];
    const uint32_t smb = smem_u32(smc);
    const int tid = threadIdx.x;
    const int wid = tid >> 5, lane = tid & 31;
    const int wm = wid >> 2, wn = wid & 3;
    const int b = blockIdx.z;
    const int m0 = blockIdx.y * 128;
    const int n0 = blockIdx.x * 128;

    const fp16* pAh = g_x1n_hi + (size_t)b * ND * CD + m0;
    const fp16* pAl = g_x1n_lo + (size_t)b * ND * CD + m0;
    const fp16* pBh = g_x2n_hi + (size_t)b * ND * CD + n0;
    const fp16* pBl = g_x2n_lo + (size_t)b * ND * CD + n0;
    float* Cp = g_attn + (size_t)b * CD * CD;

    auto issue = [&](int c, int buf) {
        const int k0 = c * 32;
        const uint32_t sb = smb + buf * STG2;
#pragma unroll
        for (int h = 0; h < 2; h++) {
            const int idx = tid + h * 256;
            const int row = idx >> 4, seg = idx & 15;
            const uint32_t so = (uint32_t)row * ROW2 + seg * 16;
            const size_t go = (size_t)(k0 + row) * CD + seg * 8;
            cp_async16(sb + so, pAh + go);
            cp_async16(sb + TEN2 + so, pAl + go);
            cp_async16(sb + 2 * TEN2 + so, pBh + go);
            cp_async16(sb + 3 * TEN2 + so, pBl + go);
        }
        CP_COMMIT();
    };

    float acc[4][4][4] = {};
    constexpr int NC = ND / 32;  // 128

    issue(0, 0);
    issue(1, 1);

    const int a_kr = ((lane >> 4) << 3) + (lane & 7);
    const int a_mc = (lane >> 3) & 1;
    const int b_kr = (((lane >> 3) & 1) << 3) + (lane & 7);
    const int b_nc = lane >> 4;

    int buf = 0;
    for (int c = 0; c < NC; c++) {
        const bool more = (c + 2 < NC);
        if (more) { CP_WAIT(1); } else { CP_WAIT(0); }
        __syncthreads();

        const uint32_t sA = smb + buf * STG2;
        const uint32_t sB = sA + 2 * TEN2;

        uint32_t ah[4][4], al[4][4], bh[2][4], bl[2][4];

        auto load_frags = [&](int ks) {
            const uint32_t akro = (uint32_t)(ks * 16 + a_kr) * ROW2;
            const uint32_t bkro = (uint32_t)(ks * 16 + b_kr) * ROW2;
#pragma unroll
            for (int mt = 0; mt < 4; mt++) {
                uint32_t addr = sA + akro + (uint32_t)(wm * 128 + mt * 32 + a_mc * 16);
                ldsm4t(ah[mt][0], ah[mt][1], ah[mt][2], ah[mt][3], addr);
                ldsm4t(al[mt][0], al[mt][1], al[mt][2], al[mt][3], addr + TEN2);
            }
#pragma unroll
            for (int np = 0; np < 2; np++) {
                uint32_t addr = sB + bkro + (uint32_t)(wn * 64 + np * 32 + b_nc * 16);
                ldsm4t(bh[np][0], bh[np][1], bh[np][2], bh[np][3], addr);
                ldsm4t(bl[np][0], bl[np][1], bl[np][2], bl[np][3], addr + TEN2);
            }
        };
        auto mma_all = [&]() {
#pragma unroll
            for (int mt = 0; mt < 4; mt++)
#pragma unroll
                for (int nt = 0; nt < 4; nt++) {
                    const uint32_t* bph = &bh[nt >> 1][(nt & 1) * 2];
                    const uint32_t* bpl = &bl[nt >> 1][(nt & 1) * 2];
                    mma_f16(acc[mt][nt], ah[mt], bph);
                    mma_f16(acc[mt][nt], ah[mt], bpl);
                    mma_f16(acc[mt][nt], al[mt], bph);
                }
        };

        load_frags(0);
        if (more) {
            int nb = buf + 2; if (nb >= 3) nb -= 3;
            issue(c + 2, nb);
        }
        mma_all();
        load_frags(1);
        mma_all();

        buf++; if (buf == 3) buf = 0;
    }

    const int er = lane >> 2, ec = (lane & 3) * 2;
#pragma unroll
    for (int mt = 0; mt < 4; mt++) {
#pragma unroll
        for (int nt = 0; nt < 4; nt++) {
            float* a4 = acc[mt][nt];
            const int row = m0 + wm * 64 + mt * 16 + er;
            const int col = n0 + wn * 32 + nt * 8 + ec;
            *(float2*)(Cp + (size_t)row * CD + col) =
                make_float2(a4[0] * kScale, a4[1] * kScale);
            *(float2*)(Cp + (size_t)(row + 8) * CD + col) =
                make_float2(a4[2] * kScale, a4[3] * kScale);
        }
    }
}

// ---------------------------------------------------------------------------
// GEMM2 (out): out[m][n] = sum_k attn[m][k]*x2[n][k], k = channel (768).
// K-contiguous, non-trans ldmatrix, 2-term (A fp16, B hi/lo).
// PERSISTENT: 296 CTAs stride over 1536 tiles (n fastest -> A reuse in L2).
// CTA tile 128x128, 256 threads, BK=32, 3-stage. Pipe fully drained at tile end.
// ---------------------------------------------------------------------------
static constexpr int ROWB = 80;
static constexpr int TEN = 128 * ROWB;      // 10240
static constexpr int STG3 = 3 * TEN;        // 30720 (Ah, Bh, Bl)
static constexpr int SM2 = 3 * STG3;        // 92160
static constexpr int G2_NTILE = (ND / 128) * (CD / 128) * BB;  // 1536
static constexpr int G2_CTAS = 296;

__global__ __launch_bounds__(256) void gemm2_kernel(float* __restrict__ Cout) {
    extern __shared__ char smc[];
    const uint32_t smb = smem_u32(smc);
    const int tid = threadIdx.x;
    const int wid = tid >> 5, lane = tid & 31;
    const int wm = wid >> 2, wn = wid & 3;

    const int a_r = lane & 15, a_h = lane >> 4;
    const int b_r = (lane & 7) + ((lane >> 4) << 3);
    const int b_h = (lane >> 3) & 1;
    const int lrow = tid >> 2;
    const int lseg = tid & 3;
    const int er = lane >> 2, ec = (lane & 3) * 2;

    for (int t = blockIdx.x; t < G2_NTILE; t += G2_CTAS) {
        const int n_i = t & 31;           // ND/128 = 32
        const int m_i = (t >> 5) % 6;     // CD/128 = 6
        const int b   = t / 192;
        const int m0 = m_i * 128;
        const int n0 = n_i * 128;

        const fp16* pAh = g_at_hi + (size_t)b * CD * CD + (size_t)m0 * CD;
        const fp16* pBh = g_x2n_hi + (size_t)b * ND * CD + (size_t)n0 * CD;
        const fp16* pBl = g_x2n_lo + (size_t)b * ND * CD + (size_t)n0 * CD;
        float* Cp = Cout + (size_t)b * CD * ND;

        auto issue = [&](int c, int buf) {
            const int k0 = c * 32;
            const uint32_t sb = smb + buf * STG3;
#pragma unroll
            for (int h = 0; h < 2; h++) {
                const int row = lrow + h * 64;
                const uint32_t so = (uint32_t)row * ROWB + lseg * 16;
                const size_t go = (size_t)row * CD + k0 + lseg * 8;
                cp_async16(sb + so, pAh + go);
                cp_async16(sb + TEN + so, pBh + go);
                cp_async16(sb + 2 * TEN + so, pBl + go);
            }
            CP_COMMIT();
        };

        float acc[4][4][4] = {};
        constexpr int NC = CD / 32;  // 24

        issue(0, 0);
        issue(1, 1);

        int buf = 0;
        for (int c = 0; c < NC; c++) {
            const bool more = (c + 2 < NC);
            if (more) { CP_WAIT(1); } else { CP_WAIT(0); }
            __syncthreads();

            const uint32_t sA = smb + buf * STG3;
            const uint32_t sB = sA + TEN;

            uint32_t ah[4][4], bh[2][4], bl[2][4];

            auto load_frags = [&](int ks) {
                const uint32_t kso = ks * 32;
#pragma unroll
                for (int mt = 0; mt < 4; mt++) {
                    uint32_t addr = sA + (uint32_t)(wm * 64 + mt * 16 + a_r) * ROWB + kso + a_h * 16;
                    ldsm4(ah[mt][0], ah[mt][1], ah[mt][2], ah[mt][3], addr);
                }
#pragma unroll
                for (int np = 0; np < 2; np++) {
                    uint32_t addr = sB + (uint32_t)(wn * 32 + np * 16 + b_r) * ROWB + kso + b_h * 16;
                    ldsm4(bh[np][0], bh[np][1], bh[np][2], bh[np][3], addr);
                    ldsm4(bl[np][0], bl[np][1], bl[np][2], bl[np][3], addr + TEN);
                }
            };
            auto mma_all = [&]() {
#pragma unroll
                for (int mt = 0; mt < 4; mt++)
#pragma unroll
                    for (int nt = 0; nt < 4; nt++) {
                        const uint32_t* bph = &bh[nt >> 1][(nt & 1) * 2];
                        const uint32_t* bpl = &bl[nt >> 1][(nt & 1) * 2];
                        mma_f16(acc[mt][nt], ah[mt], bph);
                        mma_f16(acc[mt][nt], ah[mt], bpl);
                    }
            };

            load_frags(0);
            if (more) {
                int nb = buf + 2; if (nb >= 3) nb -= 3;
                issue(c + 2, nb);
            }
            mma_all();
            load_frags(1);
            mma_all();

            buf++; if (buf == 3) buf = 0;
        }

#pragma unroll
        for (int mt = 0; mt < 4; mt++) {
#pragma unroll
            for (int nt = 0; nt < 4; nt++) {
                float* a4 = acc[mt][nt];
                const int row = m0 + wm * 64 + mt * 16 + er;
                const int col = n0 + wn * 32 + nt * 8 + ec;
                *(float2*)(Cp + (size_t)row * ND + col) = make_float2(a4[0], a4[1]);
                *(float2*)(Cp + (size_t)(row + 8) * ND + col) = make_float2(a4[2], a4[3]);
            }
        }
        // All cp.async groups drained (tail iterations use CP_WAIT(0));
        // next tile's issue(0,0)/issue(1,1) touch bufs 0,1 while stragglers
        // only hold buf (NC-1)%3 = 2 -> no hazard without an extra barrier.
    }
}

// ---------------------------------------------------------------------------
extern "C" void kernel_launch(void* const* d_in, const int* in_sizes, int n_in,
                              void* d_out, int out_size) {
    const float* x1 = (const float*)d_in[0];
    const float* x2 = (const float*)d_in[1];
    float* out = (float*)d_out;

    cudaFuncSetAttribute(gemm1_kernel,
                         cudaFuncAttributeMaxDynamicSharedMemorySize, SM1);
    cudaFuncSetAttribute(gemm2_kernel,
                         cudaFuncAttributeMaxDynamicSharedMemorySize, SM2);

    const int half = (int)((size_t)BB * ND * CD / 2048);  // 8 floats/thread
    split_kernel<<<2 * half, 256>>>(x1, x2);

    dim3 g1(CD / 128, CD / 128, BB);  // 6 x 6 x 8 = 288 CTAs (one wave)
    gemm1_kernel<<<g1, 256, SM1>>>();

    softmax_kernel<<<BB * CD, 256>>>();

    gemm2_kernel<<<G2_CTAS, 256, SM2>>>(out);
}

// round 10
// speedup vs baseline: 1.0014x; 1.0014x over previous
#include <cuda_runtime.h>
#include <cuda_fp16.h>
#include <cstdint>

#define CD 768
#define ND 4096
#define BB 8

using fp16 = __half;

// ---------------------------------------------------------------------------
// Device scratch (module-load allocated; no runtime allocs)
// ---------------------------------------------------------------------------
__device__ fp16 g_x1n_hi[(size_t)BB * ND * CD];  // x1 natural [b][n][c]
__device__ fp16 g_x1n_lo[(size_t)BB * ND * CD];
__device__ fp16 g_x2n_hi[(size_t)BB * ND * CD];  // x2 natural [b][n][c]
__device__ fp16 g_x2n_lo[(size_t)BB * ND * CD];
__device__ float g_attn[(size_t)BB * CD * CD];   // fp32 logits
__device__ fp16 g_at_hi[(size_t)BB * CD * CD];   // softmaxed attn (fp16)

__device__ __constant__ float kScale = 0.10206207261596577f;  // (768/8)^-0.5

// ---------------------------------------------------------------------------
// PTX helpers
// ---------------------------------------------------------------------------
__device__ __forceinline__ uint32_t smem_u32(const void* p) {
    uint32_t a;
    asm("{ .reg .u64 t; cvta.to.shared.u64 t, %1; cvt.u32.u64 %0, t; }" : "=r"(a) : "l"(p));
    return a;
}

__device__ __forceinline__ void cp_async16(uint32_t saddr, const void* gaddr) {
    asm volatile("cp.async.cg.shared.global [%0], [%1], 16;" :: "r"(saddr), "l"(gaddr));
}
#define CP_COMMIT() asm volatile("cp.async.commit_group;" ::: "memory")
#define CP_WAIT(n)  asm volatile("cp.async.wait_group %0;" :: "n"(n) : "memory")

__device__ __forceinline__ void ldsm4(uint32_t& r0, uint32_t& r1, uint32_t& r2,
                                      uint32_t& r3, uint32_t addr) {
    asm volatile("ldmatrix.sync.aligned.m8n8.x4.shared.b16 {%0,%1,%2,%3}, [%4];"
                 : "=r"(r0), "=r"(r1), "=r"(r2), "=r"(r3) : "r"(addr));
}
__device__ __forceinline__ void ldsm4t(uint32_t& r0, uint32_t& r1, uint32_t& r2,
                                       uint32_t& r3, uint32_t addr) {
    asm volatile("ldmatrix.sync.aligned.m8n8.x4.trans.shared.b16 {%0,%1,%2,%3}, [%4];"
                 : "=r"(r0), "=r"(r1), "=r"(r2), "=r"(r3) : "r"(addr));
}

__device__ __forceinline__ void mma_f16(float* c, const uint32_t* a, const uint32_t* b) {
    asm volatile(
        "mma.sync.aligned.m16n8k16.row.col.f32.f16.f16.f32 "
        "{%0,%1,%2,%3}, {%4,%5,%6,%7}, {%8,%9}, {%0,%1,%2,%3};"
        : "+f"(c[0]), "+f"(c[1]), "+f"(c[2]), "+f"(c[3])
        : "r"(a[0]), "r"(a[1]), "r"(a[2]), "r"(a[3]), "r"(b[0]), "r"(b[1]));
}

// ---------------------------------------------------------------------------
// Streaming fp16 split, both tensors in one launch.
// ---------------------------------------------------------------------------
__global__ __launch_bounds__(256) void split_kernel(const float* __restrict__ x1,
                                                    const float* __restrict__ x2) {
    const int half = gridDim.x >> 1;
    const float* src;
    fp16 *dh, *dl;
    int blk = blockIdx.x;
    if (blk < half) {
        src = x1; dh = g_x1n_hi; dl = g_x1n_lo;
    } else {
        src = x2; dh = g_x2n_hi; dl = g_x2n_lo;
        blk -= half;
    }
    size_t i = ((size_t)blk * 256 + threadIdx.x) * 8;
    float4 v0 = *(const float4*)(src + i);
    float4 v1 = *(const float4*)(src + i + 4);
    float f[8] = {v0.x, v0.y, v0.z, v0.w, v1.x, v1.y, v1.z, v1.w};
    fp16 h[8], l[8];
#pragma unroll
    for (int j = 0; j < 8; j++) {
        h[j] = __float2half_rn(f[j]);
        l[j] = __float2half_rn(f[j] - __half2float(h[j]));
    }
    *(uint4*)(dh + i) = *(uint4*)h;
    *(uint4*)(dl + i) = *(uint4*)l;
}

// ---------------------------------------------------------------------------
// Softmax over g_attn rows -> fp16 attn
// ---------------------------------------------------------------------------
__global__ __launch_bounds__(256) void softmax_kernel() {
    const size_t ro = (size_t)blockIdx.x * CD;
    float* p = g_attn + ro;
    const int tid = threadIdx.x;

    float v0 = p[tid], v1 = p[tid + 256], v2 = p[tid + 512];

    float m = fmaxf(fmaxf(v0, v1), v2);
#pragma unroll
    for (int o = 16; o > 0; o >>= 1) m = fmaxf(m, __shfl_xor_sync(0xffffffffu, m, o));

    __shared__ float sm[8], ss[8];
    if ((tid & 31) == 0) sm[tid >> 5] = m;
    __syncthreads();
    float bm = sm[0];
#pragma unroll
    for (int i = 1; i < 8; i++) bm = fmaxf(bm, sm[i]);

    float e0 = __expf(v0 - bm), e1 = __expf(v1 - bm), e2 = __expf(v2 - bm);
    float s = e0 + e1 + e2;
#pragma unroll
    for (int o = 16; o > 0; o >>= 1) s += __shfl_xor_sync(0xffffffffu, s, o);
    if ((tid & 31) == 0) ss[tid >> 5] = s;
    __syncthreads();
    float bs = 0.f;
#pragma unroll
    for (int i = 0; i < 8; i++) bs += ss[i];

    float inv = 1.0f / bs;
    g_at_hi[ro + tid]       = __float2half_rn(e0 * inv);
    g_at_hi[ro + tid + 256] = __float2half_rn(e1 * inv);
    g_at_hi[ro + tid + 512] = __float2half_rn(e2 * inv);
}

// ---------------------------------------------------------------------------
// GEMM1 (logits): attn[m][n] = scale * sum_k x1[k][m]*x2[k][n], k = seq dim.
// Natural [n][c] operands, ldmatrix.trans fragments.
// CTA 128x128, 256 threads, BK=32, 3-stage, one barrier per chunk.
// ---------------------------------------------------------------------------
static constexpr int ROW2 = 272;
static constexpr int TEN2 = 32 * ROW2;      // 8704
static constexpr int STG2 = 4 * TEN2;       // 34816
static constexpr int SM1 = 3 * STG2;        // 104448

__global__ __launch_bounds__(256) void gemm1_kernel() {
    extern __shared__ char smc[];
    const uint32_t smb = smem_u32(smc);
    const int tid = threadIdx.x;
    const int wid = tid >> 5, lane = tid & 31;
    const int wm = wid >> 2, wn = wid & 3;
    const int b = blockIdx.z;
    const int m0 = blockIdx.y * 128;
    const int n0 = blockIdx.x * 128;

    const fp16* pAh = g_x1n_hi + (size_t)b * ND * CD + m0;
    const fp16* pAl = g_x1n_lo + (size_t)b * ND * CD + m0;
    const fp16* pBh = g_x2n_hi + (size_t)b * ND * CD + n0;
    const fp16* pBl = g_x2n_lo + (size_t)b * ND * CD + n0;
    float* Cp = g_attn + (size_t)b * CD * CD;

    auto issue = [&](int c, int buf) {
        const int k0 = c * 32;
        const uint32_t sb = smb + buf * STG2;
#pragma unroll
        for (int h = 0; h < 2; h++) {
            const int idx = tid + h * 256;
            const int row = idx >> 4, seg = idx & 15;
            const uint32_t so = (uint32_t)row * ROW2 + seg * 16;
            const size_t go = (size_t)(k0 + row) * CD + seg * 8;
            cp_async16(sb + so, pAh + go);
            cp_async16(sb + TEN2 + so, pAl + go);
            cp_async16(sb + 2 * TEN2 + so, pBh + go);
            cp_async16(sb + 3 * TEN2 + so, pBl + go);
        }
        CP_COMMIT();
    };

    float acc[4][4][4] = {};
    constexpr int NC = ND / 32;  // 128

    issue(0, 0);
    issue(1, 1);

    const int a_kr = ((lane >> 4) << 3) + (lane & 7);
    const int a_mc = (lane >> 3) & 1;
    const int b_kr = (((lane >> 3) & 1) << 3) + (lane & 7);
    const int b_nc = lane >> 4;

    int buf = 0;
    for (int c = 0; c < NC; c++) {
        const bool more = (c + 2 < NC);
        if (more) { CP_WAIT(1); } else { CP_WAIT(0); }
        __syncthreads();

        const uint32_t sA = smb + buf * STG2;
        const uint32_t sB = sA + 2 * TEN2;

        uint32_t ah[4][4], al[4][4], bh[2][4], bl[2][4];

        auto load_frags = [&](int ks) {
            const uint32_t akro = (uint32_t)(ks * 16 + a_kr) * ROW2;
            const uint32_t bkro = (uint32_t)(ks * 16 + b_kr) * ROW2;
#pragma unroll
            for (int mt = 0; mt < 4; mt++) {
                uint32_t addr = sA + akro + (uint32_t)(wm * 128 + mt * 32 + a_mc * 16);
                ldsm4t(ah[mt][0], ah[mt][1], ah[mt][2], ah[mt][3], addr);
                ldsm4t(al[mt][0], al[mt][1], al[mt][2], al[mt][3], addr + TEN2);
            }
#pragma unroll
            for (int np = 0; np < 2; np++) {
                uint32_t addr = sB + bkro + (uint32_t)(wn * 64 + np * 32 + b_nc * 16);
                ldsm4t(bh[np][0], bh[np][1], bh[np][2], bh[np][3], addr);
                ldsm4t(bl[np][0], bl[np][1], bl[np][2], bl[np][3], addr + TEN2);
            }
        };
        auto mma_all = [&]() {
#pragma unroll
            for (int mt = 0; mt < 4; mt++)
#pragma unroll
                for (int nt = 0; nt < 4; nt++) {
                    const uint32_t* bph = &bh[nt >> 1][(nt & 1) * 2];
                    const uint32_t* bpl = &bl[nt >> 1][(nt & 1) * 2];
                    mma_f16(acc[mt][nt], ah[mt], bph);
                    mma_f16(acc[mt][nt], ah[mt], bpl);
                    mma_f16(acc[mt][nt], al[mt], bph);
                }
        };

        load_frags(0);
        if (more) {
            int nb = buf + 2; if (nb >= 3) nb -= 3;
            issue(c + 2, nb);
        }
        mma_all();
        load_frags(1);
        mma_all();

        buf++; if (buf == 3) buf = 0;
    }

    const int er = lane >> 2, ec = (lane & 3) * 2;
#pragma unroll
    for (int mt = 0; mt < 4; mt++) {
#pragma unroll
        for (int nt = 0; nt < 4; nt++) {
            float* a4 = acc[mt][nt];
            const int row = m0 + wm * 64 + mt * 16 + er;
            const int col = n0 + wn * 32 + nt * 8 + ec;
            *(float2*)(Cp + (size_t)row * CD + col) =
                make_float2(a4[0] * kScale, a4[1] * kScale);
            *(float2*)(Cp + (size_t)(row + 8) * CD + col) =
                make_float2(a4[2] * kScale, a4[3] * kScale);
        }
    }
}

// ---------------------------------------------------------------------------
// GEMM2 (out): out[m][n] = sum_k attn[m][k]*x2[n][k], k = channel (768).
// K-contiguous, non-trans ldmatrix, 2-term (A fp16, B hi/lo).
// PERSISTENT with SEAMLESS CROSS-TILE PREFETCH: the global chunk stream never
// drains; chunk q of the stream lives in buf (q mod 3), NC=24 = 0 mod 3 keeps
// the mapping consistent across tile boundaries.
// ---------------------------------------------------------------------------
static constexpr int ROWB = 80;
static constexpr int TEN = 128 * ROWB;      // 10240
static constexpr int STG3 = 3 * TEN;        // 30720 (Ah, Bh, Bl)
static constexpr int SM2 = 3 * STG3;        // 92160
static constexpr int G2_NTILE = (ND / 128) * (CD / 128) * BB;  // 1536
static constexpr int G2_CTAS = 296;

__global__ __launch_bounds__(256) void gemm2_kernel(float* __restrict__ Cout) {
    extern __shared__ char smc[];
    const uint32_t smb = smem_u32(smc);
    const int tid = threadIdx.x;
    const int wid = tid >> 5, lane = tid & 31;
    const int wm = wid >> 2, wn = wid & 3;

    const int a_r = lane & 15, a_h = lane >> 4;
    const int b_r = (lane & 7) + ((lane >> 4) << 3);
    const int b_h = (lane >> 3) & 1;
    const int lrow = tid >> 2;
    const int lseg = tid & 3;
    const int er = lane >> 2, ec = (lane & 3) * 2;

    constexpr int NC = CD / 32;  // 24

    // tile pointer computation
    auto tile_ptrs = [&](int t, const fp16*& Ah, const fp16*& Bh, const fp16*& Bl) {
        const int n_i = t & 31;
        const int m_i = (t >> 5) % 6;
        const int b   = t / 192;
        Ah = g_at_hi + (size_t)b * CD * CD + (size_t)(m_i * 128) * CD;
        Bh = g_x2n_hi + (size_t)b * ND * CD + (size_t)(n_i * 128) * CD;
        Bl = g_x2n_lo + (size_t)b * ND * CD + (size_t)(n_i * 128) * CD;
    };

    auto issue = [&](const fp16* Ah, const fp16* Bh, const fp16* Bl,
                     int c, int buf) {
        const int k0 = c * 32;
        const uint32_t sb = smb + buf * STG3;
#pragma unroll
        for (int h = 0; h < 2; h++) {
            const int row = lrow + h * 64;
            const uint32_t so = (uint32_t)row * ROWB + lseg * 16;
            const size_t go = (size_t)row * CD + k0 + lseg * 8;
            cp_async16(sb + so, Ah + go);
            cp_async16(sb + TEN + so, Bh + go);
            cp_async16(sb + 2 * TEN + so, Bl + go);
        }
        CP_COMMIT();
    };

    const fp16 *cAh, *cBh, *cBl;   // current tile
    const fp16 *nAh, *nBh, *nBl;   // next tile (valid iff has_next)

    int t = blockIdx.x;
    if (t >= G2_NTILE) return;
    tile_ptrs(t, cAh, cBh, cBl);

    // prime the stream with chunks 0,1 of the first tile
    issue(cAh, cBh, cBl, 0, 0);
    issue(cAh, cBh, cBl, 1, 1);

    while (true) {
        const int tn = t + G2_CTAS;
        const bool has_next = (tn < G2_NTILE);
        if (has_next) tile_ptrs(tn, nAh, nBh, nBl);

        float acc[4][4][4] = {};
        int buf = 0;
        for (int c = 0; c < NC; c++) {
            const int q = c + 2;  // global prefetch distance 2
            const bool pf_cur = (q < NC);
            const bool pf_nxt = (!pf_cur) && has_next;  // q-NC in {0,1}
            const bool more = pf_cur || pf_nxt;
            if (more) { CP_WAIT(1); } else { CP_WAIT(0); }
            __syncthreads();

            const uint32_t sA = smb + buf * STG3;
            const uint32_t sB = sA + TEN;

            uint32_t ah[4][4], bh[2][4], bl[2][4];

            auto load_frags = [&](int ks) {
                const uint32_t kso = ks * 32;
#pragma unroll
                for (int mt = 0; mt < 4; mt++) {
                    uint32_t addr = sA + (uint32_t)(wm * 64 + mt * 16 + a_r) * ROWB + kso + a_h * 16;
                    ldsm4(ah[mt][0], ah[mt][1], ah[mt][2], ah[mt][3], addr);
                }
#pragma unroll
                for (int np = 0; np < 2; np++) {
                    uint32_t addr = sB + (uint32_t)(wn * 32 + np * 16 + b_r) * ROWB + kso + b_h * 16;
                    ldsm4(bh[np][0], bh[np][1], bh[np][2], bh[np][3], addr);
                    ldsm4(bl[np][0], bl[np][1], bl[np][2], bl[np][3], addr + TEN);
                }
            };
            auto mma_all = [&]() {
#pragma unroll
                for (int mt = 0; mt < 4; mt++)
#pragma unroll
                    for (int nt = 0; nt < 4; nt++) {
                        const uint32_t* bph = &bh[nt >> 1][(nt & 1) * 2];
                        const uint32_t* bpl = &bl[nt >> 1][(nt & 1) * 2];
                        mma_f16(acc[mt][nt], ah[mt], bph);
                        mma_f16(acc[mt][nt], ah[mt], bpl);
                    }
            };

            load_frags(0);
            if (pf_cur) {
                int nb = buf + 2; if (nb >= 3) nb -= 3;
                issue(cAh, cBh, cBl, q, nb);
            } else if (pf_nxt) {
                int nb = buf + 2; if (nb >= 3) nb -= 3;  // == (q % 3) since NC%3==0
                issue(nAh, nBh, nBl, q - NC, nb);
            }
            mma_all();
            load_frags(1);
            mma_all();

            buf++; if (buf == 3) buf = 0;
        }

        // epilogue (overlaps the already-issued next-tile loads)
        {
            const int n_i = t & 31;
            const int m_i = (t >> 5) % 6;
            const int b   = t / 192;
            float* Cp = Cout + (size_t)b * CD * ND;
            const int m0 = m_i * 128, n0 = n_i * 128;
#pragma unroll
            for (int mt = 0; mt < 4; mt++) {
#pragma unroll
                for (int nt = 0; nt < 4; nt++) {
                    float* a4 = acc[mt][nt];
                    const int row = m0 + wm * 64 + mt * 16 + er;
                    const int col = n0 + wn * 32 + nt * 8 + ec;
                    *(float2*)(Cp + (size_t)row * ND + col) = make_float2(a4[0], a4[1]);
                    *(float2*)(Cp + (size_t)(row + 8) * ND + col) = make_float2(a4[2], a4[3]);
                }
            }
        }

        if (!has_next) break;
        t = tn;
        cAh = nAh; cBh = nBh; cBl = nBl;
        // stream already holds chunks 0,1 of the new tile in bufs 0,1
    }
}

// ---------------------------------------------------------------------------
extern "C" void kernel_launch(void* const* d_in, const int* in_sizes, int n_in,
                              void* d_out, int out_size) {
    const float* x1 = (const float*)d_in[0];
    const float* x2 = (const float*)d_in[1];
    float* out = (float*)d_out;

    cudaFuncSetAttribute(gemm1_kernel,
                         cudaFuncAttributeMaxDynamicSharedMemorySize, SM1);
    cudaFuncSetAttribute(gemm2_kernel,
                         cudaFuncAttributeMaxDynamicSharedMemorySize, SM2);

    const int half = (int)((size_t)BB * ND * CD / 2048);  // 8 floats/thread
    split_kernel<<<2 * half, 256>>>(x1, x2);

    dim3 g1(CD / 128, CD / 128, BB);  // 6 x 6 x 8 = 288 CTAs (one wave)
    gemm1_kernel<<<g1, 256, SM1>>>();

    softmax_kernel<<<BB * CD, 256>>>();

    gemm2_kernel<<<G2_CTAS, 256, SM2>>>(out);
}

// round 11
// speedup vs baseline: 1.1710x; 1.1694x over previous
#include <cuda_runtime.h>
#include <cuda_fp16.h>
#include <cstdint>

#define CD 768
#define ND 4096
#define BB 8

using fp16 = __half;

// ---------------------------------------------------------------------------
// Device scratch (module-load allocated; no runtime allocs)
// ---------------------------------------------------------------------------
__device__ fp16 g_x1n_hi[(size_t)BB * ND * CD];  // x1 natural [b][n][c]
__device__ fp16 g_x1n_lo[(size_t)BB * ND * CD];
__device__ fp16 g_x2n_hi[(size_t)BB * ND * CD];  // x2 natural [b][n][c]
__device__ fp16 g_x2n_lo[(size_t)BB * ND * CD];
__device__ float g_attn[(size_t)BB * CD * CD];   // fp32 logits
__device__ fp16 g_at_hi[(size_t)BB * CD * CD];   // softmaxed attn (fp16)

__device__ __constant__ float kScale = 0.10206207261596577f;  // (768/8)^-0.5

// ---------------------------------------------------------------------------
// PTX helpers
// ---------------------------------------------------------------------------
__device__ __forceinline__ uint32_t smem_u32(const void* p) {
    uint32_t a;
    asm("{ .reg .u64 t; cvta.to.shared.u64 t, %1; cvt.u32.u64 %0, t; }" : "=r"(a) : "l"(p));
    return a;
}

__device__ __forceinline__ void cp_async16(uint32_t saddr, const void* gaddr) {
    asm volatile("cp.async.cg.shared.global [%0], [%1], 16;" :: "r"(saddr), "l"(gaddr));
}
#define CP_COMMIT() asm volatile("cp.async.commit_group;" ::: "memory")
#define CP_WAIT(n)  asm volatile("cp.async.wait_group %0;" :: "n"(n) : "memory")

__device__ __forceinline__ void ldsm4(uint32_t& r0, uint32_t& r1, uint32_t& r2,
                                      uint32_t& r3, uint32_t addr) {
    asm volatile("ldmatrix.sync.aligned.m8n8.x4.shared.b16 {%0,%1,%2,%3}, [%4];"
                 : "=r"(r0), "=r"(r1), "=r"(r2), "=r"(r3) : "r"(addr));
}
__device__ __forceinline__ void ldsm4t(uint32_t& r0, uint32_t& r1, uint32_t& r2,
                                       uint32_t& r3, uint32_t addr) {
    asm volatile("ldmatrix.sync.aligned.m8n8.x4.trans.shared.b16 {%0,%1,%2,%3}, [%4];"
                 : "=r"(r0), "=r"(r1), "=r"(r2), "=r"(r3) : "r"(addr));
}

__device__ __forceinline__ void mma_f16(float* c, const uint32_t* a, const uint32_t* b) {
    asm volatile(
        "mma.sync.aligned.m16n8k16.row.col.f32.f16.f16.f32 "
        "{%0,%1,%2,%3}, {%4,%5,%6,%7}, {%8,%9}, {%0,%1,%2,%3};"
        : "+f"(c[0]), "+f"(c[1]), "+f"(c[2]), "+f"(c[3])
        : "r"(a[0]), "r"(a[1]), "r"(a[2]), "r"(a[3]), "r"(b[0]), "r"(b[1]));
}

// ---------------------------------------------------------------------------
// Streaming fp16 split, both tensors in one launch.
// ---------------------------------------------------------------------------
__global__ __launch_bounds__(256) void split_kernel(const float* __restrict__ x1,
                                                    const float* __restrict__ x2) {
    const int half = gridDim.x >> 1;
    const float* src;
    fp16 *dh, *dl;
    int blk = blockIdx.x;
    if (blk < half) {
        src = x1; dh = g_x1n_hi; dl = g_x1n_lo;
    } else {
        src = x2; dh = g_x2n_hi; dl = g_x2n_lo;
        blk -= half;
    }
    size_t i = ((size_t)blk * 256 + threadIdx.x) * 8;
    float4 v0 = *(const float4*)(src + i);
    float4 v1 = *(const float4*)(src + i + 4);
    float f[8] = {v0.x, v0.y, v0.z, v0.w, v1.x, v1.y, v1.z, v1.w};
    fp16 h[8], l[8];
#pragma unroll
    for (int j = 0; j < 8; j++) {
        h[j] = __float2half_rn(f[j]);
        l[j] = __float2half_rn(f[j] - __half2float(h[j]));
    }
    *(uint4*)(dh + i) = *(uint4*)h;
    *(uint4*)(dl + i) = *(uint4*)l;
}

// ---------------------------------------------------------------------------
// Softmax over g_attn rows -> fp16 attn
// ---------------------------------------------------------------------------
__global__ __launch_bounds__(256) void softmax_kernel() {
    const size_t ro = (size_t)blockIdx.x * CD;
    float* p = g_attn + ro;
    const int tid = threadIdx.x;

    float v0 = p[tid], v1 = p[tid + 256], v2 = p[tid + 512];

    float m = fmaxf(fmaxf(v0, v1), v2);
#pragma unroll
    for (int o = 16; o > 0; o >>= 1) m = fmaxf(m, __shfl_xor_sync(0xffffffffu, m, o));

    __shared__ float sm[8], ss[8];
    if ((tid & 31) == 0) sm[tid >> 5] = m;
    __syncthreads();
    float bm = sm[0];
#pragma unroll
    for (int i = 1; i < 8; i++) bm = fmaxf(bm, sm[i]);

    float e0 = __expf(v0 - bm), e1 = __expf(v1 - bm), e2 = __expf(v2 - bm);
    float s = e0 + e1 + e2;
#pragma unroll
    for (int o = 16; o > 0; o >>= 1) s += __shfl_xor_sync(0xffffffffu, s, o);
    if ((tid & 31) == 0) ss[tid >> 5] = s;
    __syncthreads();
    float bs = 0.f;
#pragma unroll
    for (int i = 0; i < 8; i++) bs += ss[i];

    float inv = 1.0f / bs;
    g_at_hi[ro + tid]       = __float2half_rn(e0 * inv);
    g_at_hi[ro + tid + 256] = __float2half_rn(e1 * inv);
    g_at_hi[ro + tid + 512] = __float2half_rn(e2 * inv);
}

// ---------------------------------------------------------------------------
// GEMM1 (logits): attn[m][n] = scale * sum_k x1[k][m]*x2[k][n], k = seq dim.
// Natural [n][c] operands, ldmatrix.trans fragments, 3-term fp16 split.
// CTA 128x128, 256 threads, BK=32, 3-stage, one barrier per chunk.
// ---------------------------------------------------------------------------
static constexpr int ROW2 = 272;
static constexpr int TEN2 = 32 * ROW2;      // 8704
static constexpr int STG2 = 4 * TEN2;       // 34816
static constexpr int SM1 = 3 * STG2;        // 104448

__global__ __launch_bounds__(256) void gemm1_kernel() {
    extern __shared__ char smc[];
    const uint32_t smb = smem_u32(smc);
    const int tid = threadIdx.x;
    const int wid = tid >> 5, lane = tid & 31;
    const int wm = wid >> 2, wn = wid & 3;
    const int b = blockIdx.z;
    const int m0 = blockIdx.y * 128;
    const int n0 = blockIdx.x * 128;

    const fp16* pAh = g_x1n_hi + (size_t)b * ND * CD + m0;
    const fp16* pAl = g_x1n_lo + (size_t)b * ND * CD + m0;
    const fp16* pBh = g_x2n_hi + (size_t)b * ND * CD + n0;
    const fp16* pBl = g_x2n_lo + (size_t)b * ND * CD + n0;
    float* Cp = g_attn + (size_t)b * CD * CD;

    auto issue = [&](int c, int buf) {
        const int k0 = c * 32;
        const uint32_t sb = smb + buf * STG2;
#pragma unroll
        for (int h = 0; h < 2; h++) {
            const int idx = tid + h * 256;
            const int row = idx >> 4, seg = idx & 15;
            const uint32_t so = (uint32_t)row * ROW2 + seg * 16;
            const size_t go = (size_t)(k0 + row) * CD + seg * 8;
            cp_async16(sb + so, pAh + go);
            cp_async16(sb + TEN2 + so, pAl + go);
            cp_async16(sb + 2 * TEN2 + so, pBh + go);
            cp_async16(sb + 3 * TEN2 + so, pBl + go);
        }
        CP_COMMIT();
    };

    float acc[4][4][4] = {};
    constexpr int NC = ND / 32;  // 128

    issue(0, 0);
    issue(1, 1);

    const int a_kr = ((lane >> 4) << 3) + (lane & 7);
    const int a_mc = (lane >> 3) & 1;
    const int b_kr = (((lane >> 3) & 1) << 3) + (lane & 7);
    const int b_nc = lane >> 4;

    int buf = 0;
    for (int c = 0; c < NC; c++) {
        const bool more = (c + 2 < NC);
        if (more) { CP_WAIT(1); } else { CP_WAIT(0); }
        __syncthreads();

        const uint32_t sA = smb + buf * STG2;
        const uint32_t sB = sA + 2 * TEN2;

        uint32_t ah[4][4], al[4][4], bh[2][4], bl[2][4];

        auto load_frags = [&](int ks) {
            const uint32_t akro = (uint32_t)(ks * 16 + a_kr) * ROW2;
            const uint32_t bkro = (uint32_t)(ks * 16 + b_kr) * ROW2;
#pragma unroll
            for (int mt = 0; mt < 4; mt++) {
                uint32_t addr = sA + akro + (uint32_t)(wm * 128 + mt * 32 + a_mc * 16);
                ldsm4t(ah[mt][0], ah[mt][1], ah[mt][2], ah[mt][3], addr);
                ldsm4t(al[mt][0], al[mt][1], al[mt][2], al[mt][3], addr + TEN2);
            }
#pragma unroll
            for (int np = 0; np < 2; np++) {
                uint32_t addr = sB + bkro + (uint32_t)(wn * 64 + np * 32 + b_nc * 16);
                ldsm4t(bh[np][0], bh[np][1], bh[np][2], bh[np][3], addr);
                ldsm4t(bl[np][0], bl[np][1], bl[np][2], bl[np][3], addr + TEN2);
            }
        };
        auto mma_all = [&]() {
#pragma unroll
            for (int mt = 0; mt < 4; mt++)
#pragma unroll
                for (int nt = 0; nt < 4; nt++) {
                    const uint32_t* bph = &bh[nt >> 1][(nt & 1) * 2];
                    const uint32_t* bpl = &bl[nt >> 1][(nt & 1) * 2];
                    mma_f16(acc[mt][nt], ah[mt], bph);
                    mma_f16(acc[mt][nt], ah[mt], bpl);
                    mma_f16(acc[mt][nt], al[mt], bph);
                }
        };

        load_frags(0);
        if (more) {
            int nb = buf + 2; if (nb >= 3) nb -= 3;
            issue(c + 2, nb);
        }
        mma_all();
        load_frags(1);
        mma_all();

        buf++; if (buf == 3) buf = 0;
    }

    const int er = lane >> 2, ec = (lane & 3) * 2;
#pragma unroll
    for (int mt = 0; mt < 4; mt++) {
#pragma unroll
        for (int nt = 0; nt < 4; nt++) {
            float* a4 = acc[mt][nt];
            const int row = m0 + wm * 64 + mt * 16 + er;
            const int col = n0 + wn * 32 + nt * 8 + ec;
            *(float2*)(Cp + (size_t)row * CD + col) =
                make_float2(a4[0] * kScale, a4[1] * kScale);
            *(float2*)(Cp + (size_t)(row + 8) * CD + col) =
                make_float2(a4[2] * kScale, a4[3] * kScale);
        }
    }
}

// ---------------------------------------------------------------------------
// GEMM2 (out): out[m][n] = sum_k attn[m][k]*x2[n][k], k = channel (768).
// K-contiguous, non-trans ldmatrix. ONE-TERM fp16 x fp16 (A = attn fp16,
// B = x2 hi only; B-rounding adds ~1.4e-4 rel err, inside budget).
// CTA 128x128, 256 threads, BK=32, 3-stage, one barrier per chunk. 2 CTAs/SM.
// ---------------------------------------------------------------------------
static constexpr int ROWB = 80;
static constexpr int TEN = 128 * ROWB;      // 10240
static constexpr int STG3 = 2 * TEN;        // 20480 (Ah, Bh)
static constexpr int SM2 = 3 * STG3;        // 61440

__global__ __launch_bounds__(256) void gemm2_kernel(float* __restrict__ Cout) {
    extern __shared__ char smc[];
    const uint32_t smb = smem_u32(smc);
    const int tid = threadIdx.x;
    const int wid = tid >> 5, lane = tid & 31;
    const int wm = wid >> 2, wn = wid & 3;
    const int b = blockIdx.z;
    const int m0 = blockIdx.y * 128;
    const int n0 = blockIdx.x * 128;

    const fp16* pAh = g_at_hi + (size_t)b * CD * CD + (size_t)m0 * CD;
    const fp16* pBh = g_x2n_hi + (size_t)b * ND * CD + (size_t)n0 * CD;
    float* Cp = Cout + (size_t)b * CD * ND;

    const int lrow = tid >> 2;
    const int lseg = tid & 3;

    auto issue = [&](int c, int buf) {
        const int k0 = c * 32;
        const uint32_t sb = smb + buf * STG3;
#pragma unroll
        for (int h = 0; h < 2; h++) {
            const int row = lrow + h * 64;
            const uint32_t so = (uint32_t)row * ROWB + lseg * 16;
            const size_t go = (size_t)row * CD + k0 + lseg * 8;
            cp_async16(sb + so, pAh + go);
            cp_async16(sb + TEN + so, pBh + go);
        }
        CP_COMMIT();
    };

    float acc[4][4][4] = {};
    constexpr int NC = CD / 32;  // 24

    issue(0, 0);
    issue(1, 1);

    const int a_r = lane & 15, a_h = lane >> 4;
    const int b_r = (lane & 7) + ((lane >> 4) << 3);
    const int b_h = (lane >> 3) & 1;

    int buf = 0;
    for (int c = 0; c < NC; c++) {
        const bool more = (c + 2 < NC);
        if (more) { CP_WAIT(1); } else { CP_WAIT(0); }
        __syncthreads();

        const uint32_t sA = smb + buf * STG3;
        const uint32_t sB = sA + TEN;

        uint32_t ah[4][4], bh[2][4];

        auto load_frags = [&](int ks) {
            const uint32_t kso = ks * 32;
#pragma unroll
            for (int mt = 0; mt < 4; mt++) {
                uint32_t addr = sA + (uint32_t)(wm * 64 + mt * 16 + a_r) * ROWB + kso + a_h * 16;
                ldsm4(ah[mt][0], ah[mt][1], ah[mt][2], ah[mt][3], addr);
            }
#pragma unroll
            for (int np = 0; np < 2; np++) {
                uint32_t addr = sB + (uint32_t)(wn * 32 + np * 16 + b_r) * ROWB + kso + b_h * 16;
                ldsm4(bh[np][0], bh[np][1], bh[np][2], bh[np][3], addr);
            }
        };
        auto mma_all = [&]() {
#pragma unroll
            for (int mt = 0; mt < 4; mt++)
#pragma unroll
                for (int nt = 0; nt < 4; nt++) {
                    const uint32_t* bph = &bh[nt >> 1][(nt & 1) * 2];
                    mma_f16(acc[mt][nt], ah[mt], bph);
                }
        };

        load_frags(0);
        if (more) {
            int nb = buf + 2; if (nb >= 3) nb -= 3;
            issue(c + 2, nb);
        }
        mma_all();
        load_frags(1);
        mma_all();

        buf++; if (buf == 3) buf = 0;
    }

    const int er = lane >> 2, ec = (lane & 3) * 2;
#pragma unroll
    for (int mt = 0; mt < 4; mt++) {
#pragma unroll
        for (int nt = 0; nt < 4; nt++) {
            float* a4 = acc[mt][nt];
            const int row = m0 + wm * 64 + mt * 16 + er;
            const int col = n0 + wn * 32 + nt * 8 + ec;
            *(float2*)(Cp + (size_t)row * ND + col) = make_float2(a4[0], a4[1]);
            *(float2*)(Cp + (size_t)(row + 8) * ND + col) = make_float2(a4[2], a4[3]);
        }
    }
}

// ---------------------------------------------------------------------------
extern "C" void kernel_launch(void* const* d_in, const int* in_sizes, int n_in,
                              void* d_out, int out_size) {
    const float* x1 = (const float*)d_in[0];
    const float* x2 = (const float*)d_in[1];
    float* out = (float*)d_out;

    cudaFuncSetAttribute(gemm1_kernel,
                         cudaFuncAttributeMaxDynamicSharedMemorySize, SM1);
    cudaFuncSetAttribute(gemm2_kernel,
                         cudaFuncAttributeMaxDynamicSharedMemorySize, SM2);

    const int half = (int)((size_t)BB * ND * CD / 2048);  // 8 floats/thread
    split_kernel<<<2 * half, 256>>>(x1, x2);

    dim3 g1(CD / 128, CD / 128, BB);  // 6 x 6 x 8 = 288 CTAs (one wave)
    gemm1_kernel<<<g1, 256, SM1>>>();

    softmax_kernel<<<BB * CD, 256>>>();

    dim3 g2(ND / 128, CD / 128, BB);  // 32 x 6 x 8 = 768 CTAs
    gemm2_kernel<<<g2, 256, SM2>>>(out);
}